// round 1
// baseline (speedup 1.0000x reference)
#include <cuda_runtime.h>
#include <math_constants.h>

#define B_ 2
#define T_ 256
#define E_ 512
#define H_ 8
#define D_ 64
#define AW_OFF (B_*T_*E_)   // 262144 floats of o, then attn_weights

// scratch (allocation-free: device globals)
__device__ float g_q[B_*H_*T_*D_];
__device__ float g_k[B_*H_*T_*D_];
__device__ float g_v[B_*H_*T_*D_];
__device__ float g_o[B_*T_*E_];

// ---------------------------------------------------------------------------
// GEMM: C[m,n] = sum_k A[m,k]*W[k,n] + bias[n]
//   M = 512 rows (b*T+t), K = 512. mode 0: N=1536, scatter into g_q/g_k/g_v.
//   mode 1: N=512, A is g_o (B,T,E), write to out (the o projection).
// 64x64 tile, 256 threads, 4x4 microtile, K-step 16.
// ---------------------------------------------------------------------------
__global__ void gemm_kernel(const float* __restrict__ A,
                            const float* __restrict__ W,
                            const float* __restrict__ bias,
                            float* __restrict__ Cout,
                            int N, int mode)
{
    __shared__ float As[16][65];   // [k][m], padded
    __shared__ float Bs[16][64];   // [k][n]

    const float* Asrc = (mode == 1) ? g_o : A;

    int tid = threadIdx.x;
    int tx = tid & 15, ty = tid >> 4;
    int m0 = blockIdx.y * 64, n0 = blockIdx.x * 64;

    float acc[4][4] = {};

    int amm = tid >> 2;            // row within A tile
    int akq = (tid & 3) * 4;       // k offset (float4)
    int bkk = tid >> 4;            // k row within B tile
    int bnn = (tid & 15) * 4;      // n offset (float4)

    for (int kt = 0; kt < 512; kt += 16) {
        float4 av = *(const float4*)&Asrc[(m0 + amm) * 512 + kt + akq];
        As[akq + 0][amm] = av.x;
        As[akq + 1][amm] = av.y;
        As[akq + 2][amm] = av.z;
        As[akq + 3][amm] = av.w;
        *(float4*)&Bs[bkk][bnn] = *(const float4*)&W[(size_t)(kt + bkk) * N + n0 + bnn];
        __syncthreads();
#pragma unroll
        for (int kk = 0; kk < 16; kk++) {
            float ar[4], br[4];
#pragma unroll
            for (int i = 0; i < 4; i++) ar[i] = As[kk][ty * 4 + i];
            float4 b4 = *(float4*)&Bs[kk][tx * 4];
            br[0] = b4.x; br[1] = b4.y; br[2] = b4.z; br[3] = b4.w;
#pragma unroll
            for (int i = 0; i < 4; i++)
#pragma unroll
                for (int j = 0; j < 4; j++)
                    acc[i][j] = fmaf(ar[i], br[j], acc[i][j]);
        }
        __syncthreads();
    }

    if (mode == 1) {
#pragma unroll
        for (int i = 0; i < 4; i++) {
            int m = m0 + ty * 4 + i;
#pragma unroll
            for (int j = 0; j < 4; j++) {
                int n = n0 + tx * 4 + j;
                Cout[(size_t)m * N + n] = acc[i][j] + bias[n];
            }
        }
    } else {
        // n0 is a multiple of 64 => whole tile belongs to one (which, h)
        int which = n0 >> 9;               // 0=q 1=k 2=v
        int h = (n0 & 511) >> 6;
        float* dst = (which == 0) ? g_q : (which == 1) ? g_k : g_v;
#pragma unroll
        for (int i = 0; i < 4; i++) {
            int m = m0 + ty * 4 + i;
            int b = m >> 8, t = m & 255;
#pragma unroll
            for (int j = 0; j < 4; j++) {
                int d = tx * 4 + j;
                dst[(((b * H_ + h) * T_ + t) * D_) + d] =
                    acc[i][j] + bias[n0 + d];
            }
        }
    }
}

// ---------------------------------------------------------------------------
// Fused rotary attention.
// grid = 128 blocks: (b, tile of 4 t rows). 256 threads: sl = s-lane (0..31),
// h = warp = head. s processed in 8 chunks of 32 (s = c*32 + sl).
// attn_mask staged into smem per chunk (shared by 8 heads). Scores kept in
// registers of warp h; softmax via warp shfl; o = a@v via shfl broadcast.
// ---------------------------------------------------------------------------
__global__ void attn_kernel(const float* __restrict__ mglob,
                            const float* __restrict__ pad,
                            float* __restrict__ outw)
{
    __shared__ float4 m_s[4][32][17];   // [tt][si][j4], pad 17 -> conflict-free
    __shared__ float aw_s[4][256];

    int tid = threadIdx.x;
    int sl = tid & 31;
    int h  = tid >> 5;
    int b  = blockIdx.x >> 6;
    int t0 = (blockIdx.x & 63) * 4;

#pragma unroll
    for (int tt = 0; tt < 4; tt++) aw_s[tt][tid] = 0.f;

    const float* kbase = g_k + (size_t)(b * H_ + h) * T_ * D_;
    const float* qbase = g_q + ((size_t)(b * H_ + h) * T_ + t0) * D_;
    const float* vbase = g_v + (size_t)(b * H_ + h) * T_ * D_;
    const float* mbase = mglob + (size_t)(b * T_ + t0) * T_ * D_;

    float sc[4][8];

    for (int c = 0; c < 8; c++) {
        __syncthreads();   // m_s reuse fence
        // stage m chunk: 32 s x 4 t x 64 floats = 2048 float4 / 256 threads
#pragma unroll
        for (int r = 0; r < 8; r++) {
            int vi = r * 256 + tid;
            int j4  = vi & 15;
            int rem = vi >> 4;
            int tt  = rem & 3;
            int si  = rem >> 2;
            float4 v = *(const float4*)(mbase + ((size_t)tt * T_ + c * 32 + si) * D_ + j4 * 4);
            m_s[tt][si][j4] = v;
        }
        __syncthreads();

        int s = c * 32 + sl;
        float kreg[64];
        const float4* kp = (const float4*)(kbase + (size_t)s * D_);
#pragma unroll
        for (int j4 = 0; j4 < 16; j4++) {
            float4 kv = kp[j4];
            kreg[4 * j4 + 0] = kv.x; kreg[4 * j4 + 1] = kv.y;
            kreg[4 * j4 + 2] = kv.z; kreg[4 * j4 + 3] = kv.w;
        }
        float pm = pad[b * T_ + s];
#pragma unroll
        for (int tt = 0; tt < 4; tt++) {
            const float4* qp = (const float4*)(qbase + tt * D_);
            float acc = 0.f;
#pragma unroll
            for (int j4 = 0; j4 < 16; j4++) {
                float4 qv = qp[j4];           // L1-broadcast across warp
                float4 mv = m_s[tt][sl][j4];
                float c0 = fmaf(qv.x, kreg[4*j4+0],  qv.y * kreg[4*j4+1]);
                float d0 = fmaf(qv.y, kreg[4*j4+0], -qv.x * kreg[4*j4+1]);
                acc = fmaf(mv.x, c0, acc);
                acc = fmaf(mv.y, d0, acc);
                float c1 = fmaf(qv.z, kreg[4*j4+2],  qv.w * kreg[4*j4+3]);
                float d1 = fmaf(qv.w, kreg[4*j4+2], -qv.z * kreg[4*j4+3]);
                acc = fmaf(mv.z, c1, acc);
                acc = fmaf(mv.w, d1, acc);
            }
            sc[tt][c] = acc * 0.125f + pm;    // scale = 1/sqrt(64)
        }
    }

    // softmax over s (row (tt,h) lives entirely in warp h: 32 lanes x 8 chunks)
    const unsigned FULL = 0xffffffffu;
    float aval[4][8];
#pragma unroll
    for (int tt = 0; tt < 4; tt++) {
        float mx = -CUDART_INF_F;
#pragma unroll
        for (int c = 0; c < 8; c++) mx = fmaxf(mx, sc[tt][c]);
#pragma unroll
        for (int o = 16; o > 0; o >>= 1) mx = fmaxf(mx, __shfl_xor_sync(FULL, mx, o));
        float sum = 0.f;
#pragma unroll
        for (int c = 0; c < 8; c++) {
            float e = __expf(sc[tt][c] - mx);
            aval[tt][c] = e;
            sum += e;
        }
#pragma unroll
        for (int o = 16; o > 0; o >>= 1) sum += __shfl_xor_sync(FULL, sum, o);
        float r = 1.f / sum;
#pragma unroll
        for (int c = 0; c < 8; c++) aval[tt][c] *= r;
    }

    // attn_weights accumulation: sum over heads / H
#pragma unroll
    for (int tt = 0; tt < 4; tt++)
#pragma unroll
        for (int c = 0; c < 8; c++)
            atomicAdd(&aw_s[tt][c * 32 + sl], aval[tt][c] * 0.125f);

    // o = a @ v : lane sl owns d = {2sl, 2sl+1}; broadcast a via shfl
    float oa[4][2] = {};
    int d0 = 2 * sl;
    for (int c = 0; c < 8; c++) {
#pragma unroll
        for (int sp = 0; sp < 32; sp++) {
            float a0 = __shfl_sync(FULL, aval[0][c], sp);
            float a1 = __shfl_sync(FULL, aval[1][c], sp);
            float a2 = __shfl_sync(FULL, aval[2][c], sp);
            float a3 = __shfl_sync(FULL, aval[3][c], sp);
            float2 vv = *(const float2*)(vbase + (size_t)(c * 32 + sp) * D_ + d0);
            oa[0][0] = fmaf(a0, vv.x, oa[0][0]); oa[0][1] = fmaf(a0, vv.y, oa[0][1]);
            oa[1][0] = fmaf(a1, vv.x, oa[1][0]); oa[1][1] = fmaf(a1, vv.y, oa[1][1]);
            oa[2][0] = fmaf(a2, vv.x, oa[2][0]); oa[2][1] = fmaf(a2, vv.y, oa[2][1]);
            oa[3][0] = fmaf(a3, vv.x, oa[3][0]); oa[3][1] = fmaf(a3, vv.y, oa[3][1]);
        }
    }
#pragma unroll
    for (int tt = 0; tt < 4; tt++) {
        float2 w2 = make_float2(oa[tt][0], oa[tt][1]);
        *(float2*)&g_o[(((size_t)(b * T_ + t0 + tt)) * H_ + h) * D_ + d0] = w2;
    }

    __syncthreads();
#pragma unroll
    for (int tt = 0; tt < 4; tt++)
        outw[AW_OFF + ((size_t)(b * T_ + t0 + tt)) * T_ + tid] = aw_s[tt][tid];
}

// ---------------------------------------------------------------------------
extern "C" void kernel_launch(void* const* d_in, const int* in_sizes, int n_in,
                              void* d_out, int out_size)
{
    const float* x    = (const float*)d_in[0];
    const float* am   = (const float*)d_in[1];
    const float* pm   = (const float*)d_in[2];
    const float* Wqkv = (const float*)d_in[3];
    const float* bqkv = (const float*)d_in[4];
    const float* Wo   = (const float*)d_in[5];
    const float* bo   = (const float*)d_in[6];
    float* out = (float*)d_out;

    // QKV projection + head scatter
    gemm_kernel<<<dim3(24, 8), 256>>>(x, Wqkv, bqkv, nullptr, 1536, 0);
    // fused rotary attention (+ attn_weights part of output)
    attn_kernel<<<128, 256>>>(am, pm, out);
    // output projection
    gemm_kernel<<<dim3(8, 8), 256>>>(nullptr, Wo, bo, out, 512, 1);
}

// round 3
// speedup vs baseline: 1.0271x; 1.0271x over previous
#include <cuda_runtime.h>
#include <math_constants.h>

typedef unsigned long long ull;

#define B_ 2
#define T_ 256
#define E_ 512
#define H_ 8
#define D_ 64
#define AW_OFF (B_*T_*E_)

// scratch (allocation-free: device globals)
__device__ float g_q[B_*H_*T_*D_];        // [b][h][t][pp][4] : (e_p, e_p+16, o_p, o_p+16)
__device__ float g_k[B_*H_*16*T_*4];      // [b][h][pp][s][4] : transposed for coalesced attn loads
__device__ float g_v[B_*H_*T_*D_];        // natural [b][h][s][d]
__device__ float g_o[B_*T_*E_];           // [b*T+t][h*64+d]

// ---- packed f32x2 helpers -------------------------------------------------
__device__ __forceinline__ ull pk2(float lo, float hi) {
    ull r; asm("mov.b64 %0,{%1,%2};" : "=l"(r) : "f"(lo), "f"(hi)); return r;
}
__device__ __forceinline__ void upk2(ull v, float& a, float& b) {
    asm("mov.b64 {%0,%1},%2;" : "=f"(a), "=f"(b) : "l"(v));
}
__device__ __forceinline__ ull ffma2(ull a, ull b, ull c) {
    ull d; asm("fma.rn.f32x2 %0,%1,%2,%3;" : "=l"(d) : "l"(a), "l"(b), "l"(c)); return d;
}
__device__ __forceinline__ ull fmul2(ull a, ull b) {
    ull d; asm("mul.rn.f32x2 %0,%1,%2;" : "=l"(d) : "l"(a), "l"(b)); return d;
}

// ---------------------------------------------------------------------------
// GEMM: C[m,n] = sum_k A[m,k]*W[k,n] + bias[n].  BN=64, BK=16, 128 threads,
// microtile TM x 8 with packed f32x2 accumulation over n-pairs.
// mode 0: A = x, N = 1536, scatter to g_q (pp layout) / g_k (transposed) / g_v.
// mode 1: A = g_o, N = 512, write Cout.
// ---------------------------------------------------------------------------
template<int BM, int TM>
__global__ __launch_bounds__(128) void gemm_kernel(const float* __restrict__ A,
                            const float* __restrict__ W,
                            const float* __restrict__ bias,
                            float* __restrict__ Cout,
                            int N, int mode)
{
    __shared__ float As[16][BM + 4];   // [k][m], row stride multiple of 4 floats
    __shared__ float Bs[16][64];       // [k][n]

    const float* Asrc = (mode == 1) ? g_o : A;

    int tid = threadIdx.x;
    int tx = tid & 7;          // 8 col-groups of 8
    int ty = tid >> 3;         // 16 row-groups of TM
    int m0 = blockIdx.y * BM, n0 = blockIdx.x * 64;

    ull acc[TM][4];
#pragma unroll
    for (int i = 0; i < TM; i++)
#pragma unroll
        for (int j = 0; j < 4; j++) acc[i][j] = pk2(0.f, 0.f);

    for (int kt = 0; kt < 512; kt += 16) {
#pragma unroll
        for (int r = 0; r < BM / 32; r++) {
            int idx = r * 128 + tid;
            int arow = idx >> 2, ac4 = (idx & 3) * 4;
            float4 v = *(const float4*)&Asrc[(size_t)(m0 + arow) * 512 + kt + ac4];
            As[ac4 + 0][arow] = v.x;
            As[ac4 + 1][arow] = v.y;
            As[ac4 + 2][arow] = v.z;
            As[ac4 + 3][arow] = v.w;
        }
#pragma unroll
        for (int r = 0; r < 2; r++) {
            int idx = r * 128 + tid;
            int brow = idx >> 4, bc4 = (idx & 15) * 4;
            *(float4*)&Bs[brow][bc4] =
                *(const float4*)&W[(size_t)(kt + brow) * N + n0 + bc4];
        }
        __syncthreads();
#pragma unroll
        for (int kk = 0; kk < 16; kk++) {
            float ar[TM];
            if (TM == 4) {
                float4 a4 = *(float4*)&As[kk][ty * 4];
                ar[0] = a4.x; ar[1] = a4.y; ar[2] = a4.z; ar[3] = a4.w;
            } else {
                float2 a2 = *(float2*)&As[kk][ty * 2];
                ar[0] = a2.x; ar[1] = a2.y;
            }
            double2 b0 = *(double2*)&Bs[kk][tx * 8];
            double2 b1 = *(double2*)&Bs[kk][tx * 8 + 4];
            ull bp[4];
            bp[0] = __double_as_longlong(b0.x);
            bp[1] = __double_as_longlong(b0.y);
            bp[2] = __double_as_longlong(b1.x);
            bp[3] = __double_as_longlong(b1.y);
#pragma unroll
            for (int i = 0; i < TM; i++) {
                ull ad = pk2(ar[i], ar[i]);
#pragma unroll
                for (int j = 0; j < 4; j++)
                    acc[i][j] = ffma2(ad, bp[j], acc[i][j]);
            }
        }
        __syncthreads();
    }

    if (mode == 1) {
#pragma unroll
        for (int i = 0; i < TM; i++) {
            int m = m0 + ty * TM + i;
#pragma unroll
            for (int j = 0; j < 4; j++) {
                float x, y; upk2(acc[i][j], x, y);
                int n = n0 + tx * 8 + j * 2;
                Cout[(size_t)m * N + n]     = x + bias[n];
                Cout[(size_t)m * N + n + 1] = y + bias[n + 1];
            }
        }
    } else {
        int which = n0 >> 9;               // 0=q 1=k 2=v
        int h = (n0 & 511) >> 6;
#pragma unroll
        for (int i = 0; i < TM; i++) {
            int m = m0 + ty * TM + i;
            int b = m >> 8, t = m & 255;
#pragma unroll
            for (int j = 0; j < 4; j++) {
                float x, y; upk2(acc[i][j], x, y);
#pragma unroll
                for (int u = 0; u < 2; u++) {
                    int d = tx * 8 + j * 2 + u;
                    float val = (u ? y : x) + bias[n0 + d];
                    if (which == 2) {
                        g_v[(((size_t)(b * H_ + h) * T_ + t) * D_) + d] = val;
                    } else {
                        int p = d >> 1, cmp = d & 1;
                        int pp = p & 15, hf = p >> 4;
                        if (which == 0)
                            g_q[(((size_t)(b * H_ + h) * T_ + t) * D_) + pp * 4 + cmp * 2 + hf] = val;
                        else
                            g_k[((((size_t)(b * H_ + h) * 16 + pp) * T_) + t) * 4 + cmp * 2 + hf] = val;
                    }
                }
            }
        }
    }
}

// ---------------------------------------------------------------------------
// Fused rotary attention, packed f32x2.
// grid = 128: (b, tile of 4 t rows). 512 threads: sl = s-lane, h = head (warp),
// g = warp-group (handles tt = 2g, 2g+1). s in 8 chunks of 32.
// m staged per chunk in smem packed over (p, p+16); q staged once (with -e copy).
// Score per pair p:  m_e*(q_e k_e + q_o k_o) + m_o*(q_o k_e - q_e k_o)
// ---------------------------------------------------------------------------
__global__ __launch_bounds__(512) void attn_kernel(const float* __restrict__ mglob,
                            const float* __restrict__ pad,
                            float* __restrict__ outw)
{
    __shared__ ull m_s[4][16][2][32];     // 32 KB, lane-major -> conflict-free LDS.64
    __shared__ float4 q4_s[8][4][16];     // 8 KB  (e,e16,o,o16) per pp
    __shared__ ull   qen_s[8][4][16];     // 4 KB  (-e,-e16)
    float* av_s = (float*)m_s;            // reuse as av[4][8][256] after score phase

    int tid = threadIdx.x;
    int sl = tid & 31;
    int h  = (tid >> 5) & 7;
    int g  = tid >> 8;
    int b  = blockIdx.x >> 6;
    int t0 = (blockIdx.x & 63) * 4;

    // stage q once: 512 items = 8h x 4tt x 16pp
    {
        int hh = tid >> 6, tt = (tid >> 4) & 3, pp = tid & 15;
        float4 f = *(const float4*)&g_q[(((size_t)(b * H_ + hh) * T_) + (t0 + tt)) * D_ + pp * 4];
        q4_s[hh][tt][pp] = f;
        qen_s[hh][tt][pp] = pk2(-f.x, -f.y);   // negated EVEN components
    }

    const double2* kT = (const double2*)g_k + (size_t)(b * H_ + h) * 16 * T_;
    const float*   vbase = g_v + (size_t)(b * H_ + h) * T_ * D_;
    const float*   mbase = mglob + (size_t)(b * T_ + t0) * T_ * D_;

    int tta = g * 2, ttb = g * 2 + 1;
    float sc[2][8];

#pragma unroll
    for (int c = 0; c < 8; c++) {
        __syncthreads();    // m_s reuse fence (also publishes q_s on c=0)
        // stage m chunk: 1024 items = 4tt x 32si x 8j4h, rearranged to (p,p+16) packs
#pragma unroll
        for (int it = 0; it < 2; it++) {
            int idx = it * 512 + tid;
            int j4h = idx & 7, si = (idx >> 3) & 31, tt = idx >> 8;
            const float* row = mbase + ((size_t)tt * T_ + c * 32 + si) * D_;
            float4 v1 = *(const float4*)(row + j4h * 4);
            float4 v2 = *(const float4*)(row + (j4h + 8) * 4);
            int pp0 = 2 * j4h, pp1 = 2 * j4h + 1;
            m_s[tt][pp0][0][si] = pk2(v1.x, v2.x);
            m_s[tt][pp0][1][si] = pk2(v1.y, v2.y);
            m_s[tt][pp1][0][si] = pk2(v1.z, v2.z);
            m_s[tt][pp1][1][si] = pk2(v1.w, v2.w);
        }
        __syncthreads();

        int s = c * 32 + sl;
        float pm = pad[b * T_ + s];
        ull a0 = pk2(0.f, 0.f), a1 = a0;
#pragma unroll
        for (int pp = 0; pp < 16; pp++) {
            double2 kd = kT[pp * T_ + s];        // coalesced: lanes contiguous in s
            ull ke = __double_as_longlong(kd.x);
            ull ko = __double_as_longlong(kd.y);
            {
                double2 q2 = *(const double2*)&q4_s[h][tta][pp];
                ull qe = __double_as_longlong(q2.x);
                ull qo = __double_as_longlong(q2.y);
                ull qen = qen_s[h][tta][pp];          // = -qe
                ull me = m_s[tta][pp][0][sl];
                ull mo = m_s[tta][pp][1][sl];
                ull cc = ffma2(qo, ko, fmul2(qe, ke));   // q_e k_e + q_o k_o
                ull dd = ffma2(qen, ko, fmul2(qo, ke));  // q_o k_e - q_e k_o
                a0 = ffma2(me, cc, a0);
                a0 = ffma2(mo, dd, a0);
            }
            {
                double2 q2 = *(const double2*)&q4_s[h][ttb][pp];
                ull qe = __double_as_longlong(q2.x);
                ull qo = __double_as_longlong(q2.y);
                ull qen = qen_s[h][ttb][pp];
                ull me = m_s[ttb][pp][0][sl];
                ull mo = m_s[ttb][pp][1][sl];
                ull cc = ffma2(qo, ko, fmul2(qe, ke));
                ull dd = ffma2(qen, ko, fmul2(qo, ke));
                a1 = ffma2(me, cc, a1);
                a1 = ffma2(mo, dd, a1);
            }
        }
        float x, y;
        upk2(a0, x, y); sc[0][c] = (x + y) * 0.125f + pm;
        upk2(a1, x, y); sc[1][c] = (x + y) * 0.125f + pm;
    }

    // softmax: row (tt,h) lives in one warp (32 lanes x 8 chunks)
    const unsigned FULL = 0xffffffffu;
    float aval[2][8];
#pragma unroll
    for (int u = 0; u < 2; u++) {
        float mx = -CUDART_INF_F;
#pragma unroll
        for (int c = 0; c < 8; c++) mx = fmaxf(mx, sc[u][c]);
#pragma unroll
        for (int o = 16; o > 0; o >>= 1) mx = fmaxf(mx, __shfl_xor_sync(FULL, mx, o));
        float sum = 0.f;
#pragma unroll
        for (int c = 0; c < 8; c++) {
            float e = __expf(sc[u][c] - mx);
            aval[u][c] = e;
            sum += e;
        }
#pragma unroll
        for (int o = 16; o > 0; o >>= 1) sum += __shfl_xor_sync(FULL, sum, o);
        float r = 1.f / sum;
#pragma unroll
        for (int c = 0; c < 8; c++) aval[u][c] *= r;
    }

    // o = a @ v : lane owns d = {2sl, 2sl+1}; broadcast a via shfl; packed fma
    ull oa[2] = { pk2(0.f, 0.f), pk2(0.f, 0.f) };
#pragma unroll
    for (int c = 0; c < 8; c++) {
#pragma unroll
        for (int sp = 0; sp < 32; sp++) {
            ull vv = *(const ull*)(vbase + (size_t)(c * 32 + sp) * D_ + 2 * sl);
            float av0 = __shfl_sync(FULL, aval[0][c], sp);
            float av1 = __shfl_sync(FULL, aval[1][c], sp);
            oa[0] = ffma2(pk2(av0, av0), vv, oa[0]);
            oa[1] = ffma2(pk2(av1, av1), vv, oa[1]);
        }
    }
#pragma unroll
    for (int u = 0; u < 2; u++) {
        int tt = g * 2 + u;
        *(ull*)&g_o[((size_t)(b * T_ + t0 + tt) * H_ + h) * D_ + 2 * sl] = oa[u];
    }

    // attn_weights: transpose-reduce over heads via smem (reuses m_s)
    __syncthreads();   // all score-phase m_s reads complete
#pragma unroll
    for (int u = 0; u < 2; u++)
#pragma unroll
        for (int c = 0; c < 8; c++)
            av_s[(size_t)(g * 2 + u) * 2048 + h * 256 + c * 32 + sl] = aval[u][c];
    __syncthreads();
#pragma unroll
    for (int it = 0; it < 2; it++) {
        int idx = it * 512 + tid;
        int tt = idx >> 8, s5 = idx & 255;
        float acc = 0.f;
#pragma unroll
        for (int hh = 0; hh < 8; hh++) acc += av_s[(size_t)tt * 2048 + hh * 256 + s5];
        outw[AW_OFF + (size_t)(b * T_ + t0 + tt) * T_ + s5] = acc * 0.125f;
    }
}

// ---------------------------------------------------------------------------
extern "C" void kernel_launch(void* const* d_in, const int* in_sizes, int n_in,
                              void* d_out, int out_size)
{
    const float* x    = (const float*)d_in[0];
    const float* am   = (const float*)d_in[1];
    const float* pm   = (const float*)d_in[2];
    const float* Wqkv = (const float*)d_in[3];
    const float* bqkv = (const float*)d_in[4];
    const float* Wo   = (const float*)d_in[5];
    const float* bo   = (const float*)d_in[6];
    float* out = (float*)d_out;

    // QKV projection + head scatter (q: pp-pack layout, k: transposed, v: natural)
    gemm_kernel<64, 4><<<dim3(24, 8), 128>>>(x, Wqkv, bqkv, nullptr, 1536, 0);
    // fused rotary attention (+ attn_weights half of output)
    attn_kernel<<<128, 512>>>(am, pm, out);
    // output projection
    gemm_kernel<32, 2><<<dim3(8, 16), 128>>>(nullptr, Wo, bo, out, 512, 1);
}

// round 4
// speedup vs baseline: 1.2852x; 1.2513x over previous
#include <cuda_runtime.h>
#include <math_constants.h>

typedef unsigned long long ull;

#define B_ 2
#define T_ 256
#define E_ 512
#define H_ 8
#define D_ 64
#define AW_OFF (B_*T_*E_)

// scratch (allocation-free: device globals)
__device__ float g_q[B_*H_*T_*D_];        // [b][h][t][pp][4] : (e_p, e_p+16, o_p, o_p+16)
__device__ float g_k[B_*H_*16*T_*4];      // [b][h][pp][s][4] : transposed, coalesced in s
__device__ float g_v[B_*H_*T_*D_];        // natural [b][h][s][d]
__device__ float g_o[B_*T_*E_];           // [b*T+t][h*64+d]

// ---- packed f32x2 helpers -------------------------------------------------
__device__ __forceinline__ ull pk2(float lo, float hi) {
    ull r; asm("mov.b64 %0,{%1,%2};" : "=l"(r) : "f"(lo), "f"(hi)); return r;
}
__device__ __forceinline__ void upk2(ull v, float& a, float& b) {
    asm("mov.b64 {%0,%1},%2;" : "=f"(a), "=f"(b) : "l"(v));
}
__device__ __forceinline__ ull ffma2(ull a, ull b, ull c) {
    ull d; asm("fma.rn.f32x2 %0,%1,%2,%3;" : "=l"(d) : "l"(a), "l"(b), "l"(c)); return d;
}
__device__ __forceinline__ ull fmul2(ull a, ull b) {
    ull d; asm("mul.rn.f32x2 %0,%1,%2;" : "=l"(d) : "l"(a), "l"(b)); return d;
}
__device__ __forceinline__ ull fadd2(ull a, ull b) {
    ull d; asm("add.rn.f32x2 %0,%1,%2;" : "=l"(d) : "l"(a), "l"(b)); return d;
}

// ---------------------------------------------------------------------------
// GEMM: C = A(512xK512) @ W(512xN) + bias. 256 threads, BMx64 tile, BK=16,
// double-buffered smem, microtile TM x 4 (2 packed n-pairs).
// mode 0: A = x, N = 1536, scatter to g_q/g_k/g_v. mode 1: A = g_o, write Cout.
// ---------------------------------------------------------------------------
template<int BM, int TM>
__global__ __launch_bounds__(256) void gemm_kernel(const float* __restrict__ A,
                            const float* __restrict__ W,
                            const float* __restrict__ bias,
                            float* __restrict__ Cout,
                            int N, int mode)
{
    __shared__ float As[2][16][BM + 4];
    __shared__ float Bs[2][16][64];

    const float* Asrc = (mode == 1) ? g_o : A;

    int tid = threadIdx.x;
    int tx = tid & 15;         // 16 col-groups of 4 (2 packed pairs)
    int ty = tid >> 4;         // 16 row-groups of TM
    int m0 = blockIdx.y * BM, n0 = blockIdx.x * 64;

    int arow = tid >> 2, ac4 = (tid & 3) * 4;   // A loader (arow < BM active)
    int brow = tid >> 4, bc4 = (tid & 15) * 4;  // B loader

    ull acc[TM][2];
#pragma unroll
    for (int i = 0; i < TM; i++) { acc[i][0] = pk2(0.f, 0.f); acc[i][1] = acc[i][0]; }

    float4 ra, rb;
    // prologue: kt = 0
    if (arow < BM) ra = *(const float4*)&Asrc[(size_t)(m0 + arow) * 512 + ac4];
    rb = *(const float4*)&W[(size_t)brow * N + n0 + bc4];
    if (arow < BM) {
        As[0][ac4 + 0][arow] = ra.x; As[0][ac4 + 1][arow] = ra.y;
        As[0][ac4 + 2][arow] = ra.z; As[0][ac4 + 3][arow] = ra.w;
    }
    *(float4*)&Bs[0][brow][bc4] = rb;
    __syncthreads();

    for (int kt16 = 0; kt16 < 32; kt16++) {
        int cur = kt16 & 1;
        if (kt16 < 31) {
            int kt = (kt16 + 1) * 16;
            if (arow < BM) ra = *(const float4*)&Asrc[(size_t)(m0 + arow) * 512 + kt + ac4];
            rb = *(const float4*)&W[(size_t)(kt + brow) * N + n0 + bc4];
        }
#pragma unroll
        for (int kk = 0; kk < 16; kk++) {
            float ar[TM];
            if (TM == 4) {
                float4 a4 = *(const float4*)&As[cur][kk][ty * 4];
                ar[0] = a4.x; ar[1] = a4.y; ar[2] = a4.z; ar[3] = a4.w;
            } else {
                float2 a2 = *(const float2*)&As[cur][kk][ty * 2];
                ar[0] = a2.x; ar[1] = a2.y;
            }
            double2 b2 = *(const double2*)&Bs[cur][kk][tx * 4];
            ull bp0 = __double_as_longlong(b2.x);
            ull bp1 = __double_as_longlong(b2.y);
#pragma unroll
            for (int i = 0; i < TM; i++) {
                ull ad = pk2(ar[i], ar[i]);
                acc[i][0] = ffma2(ad, bp0, acc[i][0]);
                acc[i][1] = ffma2(ad, bp1, acc[i][1]);
            }
        }
        if (kt16 < 31) {
            int nxt = cur ^ 1;
            if (arow < BM) {
                As[nxt][ac4 + 0][arow] = ra.x; As[nxt][ac4 + 1][arow] = ra.y;
                As[nxt][ac4 + 2][arow] = ra.z; As[nxt][ac4 + 3][arow] = ra.w;
            }
            *(float4*)&Bs[nxt][brow][bc4] = rb;
        }
        __syncthreads();
    }

    if (mode == 1) {
#pragma unroll
        for (int i = 0; i < TM; i++) {
            int m = m0 + ty * TM + i;
#pragma unroll
            for (int j = 0; j < 2; j++) {
                float x, y; upk2(acc[i][j], x, y);
                int n = n0 + tx * 4 + j * 2;
                Cout[(size_t)m * N + n]     = x + bias[n];
                Cout[(size_t)m * N + n + 1] = y + bias[n + 1];
            }
        }
    } else {
        int which = n0 >> 9;               // 0=q 1=k 2=v
        int h = (n0 & 511) >> 6;
#pragma unroll
        for (int i = 0; i < TM; i++) {
            int m = m0 + ty * TM + i;
            int b = m >> 8, t = m & 255;
#pragma unroll
            for (int j = 0; j < 2; j++) {
                float x, y; upk2(acc[i][j], x, y);
#pragma unroll
                for (int u = 0; u < 2; u++) {
                    int d = tx * 4 + j * 2 + u;
                    float val = (u ? y : x) + bias[n0 + d];
                    if (which == 2) {
                        g_v[(((size_t)(b * H_ + h) * T_ + t) * D_) + d] = val;
                    } else {
                        int p = d >> 1, cmp = d & 1;
                        int pp = p & 15, hf = p >> 4;
                        if (which == 0)
                            g_q[(((size_t)(b * H_ + h) * T_ + t) * D_) + pp * 4 + cmp * 2 + hf] = val;
                        else
                            g_k[((((size_t)(b * H_ + h) * 16 + pp) * T_) + t) * 4 + cmp * 2 + hf] = val;
                    }
                }
            }
        }
    }
}

// ---------------------------------------------------------------------------
// Fused rotary attention. grid = 256: (b, 2 t-rows). 256 threads: warp = head,
// lanes = s within chunk. m register-double-buffered; A*V via smem-a (no shfl).
// Score per pair p:  m_e*(q_e k_e + q_o k_o) + m_o*(q_o k_e - q_e k_o)
// ---------------------------------------------------------------------------
__global__ __launch_bounds__(256) void attn_kernel(const float* __restrict__ mglob,
                            const float* __restrict__ pad,
                            float* __restrict__ outw)
{
    __shared__ ull m_s[2][16][2][32];     // 16 KB, lane-major -> conflict-free LDS.64
    __shared__ float4 q4_s[8][2][16];     // 4 KB
    __shared__ ull   qen_s[8][2][16];     // 2 KB  (-e, -e16)
    float* av_s = (float*)m_s;            // reused as av[2][8][256] after scores

    int tid = threadIdx.x;
    int sl = tid & 31;
    int h  = tid >> 5;
    int b  = blockIdx.x >> 7;
    int t0 = (blockIdx.x & 127) * 2;

    // stage q once: 256 items = 8h x 2tt x 16pp
    {
        int hh = tid >> 5, tt = (tid >> 4) & 1, pp = tid & 15;
        float4 f = *(const float4*)&g_q[(((size_t)(b * H_ + hh) * T_) + (t0 + tt)) * D_ + pp * 4];
        q4_s[hh][tt][pp] = f;
        qen_s[hh][tt][pp] = pk2(-f.x, -f.y);   // negated EVEN components
    }

    const double2* kT = (const double2*)g_k + (size_t)(b * H_ + h) * 16 * T_;
    const float*   vbase = g_v + (size_t)(b * H_ + h) * T_ * D_;
    const float*   mbase = mglob + (size_t)(b * T_ + t0) * T_ * D_;

    // m staging loader indices (2 items/thread)
    int j4h_[2], si_[2], tt_[2];
#pragma unroll
    for (int it = 0; it < 2; it++) {
        int idx = it * 256 + tid;
        j4h_[it] = idx & 7; si_[it] = (idx >> 3) & 31; tt_[it] = idx >> 8;
    }

    float4 rv1[2], rv2[2];
#pragma unroll
    for (int it = 0; it < 2; it++) {   // prefetch chunk 0
        const float* row = mbase + ((size_t)tt_[it] * T_ + si_[it]) * D_;
        rv1[it] = *(const float4*)(row + j4h_[it] * 4);
        rv2[it] = *(const float4*)(row + (j4h_[it] + 8) * 4);
    }

    float sc[2][8];

#pragma unroll
    for (int c = 0; c < 8; c++) {
        __syncthreads();                // prev chunk's m_s reads done
#pragma unroll
        for (int it = 0; it < 2; it++) {
            int p0 = 2 * j4h_[it], p1 = p0 + 1, tt = tt_[it], si = si_[it];
            m_s[tt][p0][0][si] = pk2(rv1[it].x, rv2[it].x);
            m_s[tt][p0][1][si] = pk2(rv1[it].y, rv2[it].y);
            m_s[tt][p1][0][si] = pk2(rv1[it].z, rv2[it].z);
            m_s[tt][p1][1][si] = pk2(rv1[it].w, rv2[it].w);
        }
        if (c < 7) {                    // prefetch next chunk (overlaps compute)
#pragma unroll
            for (int it = 0; it < 2; it++) {
                const float* row = mbase + ((size_t)tt_[it] * T_ + (c + 1) * 32 + si_[it]) * D_;
                rv1[it] = *(const float4*)(row + j4h_[it] * 4);
                rv2[it] = *(const float4*)(row + (j4h_[it] + 8) * 4);
            }
        }
        __syncthreads();                // m_s (and on c=0, q_s) published

        int s = c * 32 + sl;
        float pm = pad[b * T_ + s];
        ull a0 = pk2(0.f, 0.f), a1 = a0;
#pragma unroll
        for (int pp = 0; pp < 16; pp++) {
            double2 kd = kT[pp * T_ + s];       // coalesced in s
            ull ke = __double_as_longlong(kd.x);
            ull ko = __double_as_longlong(kd.y);
            {
                double2 q2 = *(const double2*)&q4_s[h][0][pp];
                ull qe = __double_as_longlong(q2.x);
                ull qo = __double_as_longlong(q2.y);
                ull qen = qen_s[h][0][pp];
                ull me = m_s[0][pp][0][sl];
                ull mo = m_s[0][pp][1][sl];
                ull cc = ffma2(qo, ko, fmul2(qe, ke));   // q_e k_e + q_o k_o
                ull dd = ffma2(qen, ko, fmul2(qo, ke));  // q_o k_e - q_e k_o
                a0 = ffma2(me, cc, a0);
                a0 = ffma2(mo, dd, a0);
            }
            {
                double2 q2 = *(const double2*)&q4_s[h][1][pp];
                ull qe = __double_as_longlong(q2.x);
                ull qo = __double_as_longlong(q2.y);
                ull qen = qen_s[h][1][pp];
                ull me = m_s[1][pp][0][sl];
                ull mo = m_s[1][pp][1][sl];
                ull cc = ffma2(qo, ko, fmul2(qe, ke));
                ull dd = ffma2(qen, ko, fmul2(qo, ke));
                a1 = ffma2(me, cc, a1);
                a1 = ffma2(mo, dd, a1);
            }
        }
        float x, y;
        upk2(a0, x, y); sc[0][c] = (x + y) * 0.125f + pm;
        upk2(a1, x, y); sc[1][c] = (x + y) * 0.125f + pm;
    }

    // softmax: row (tt,h) lives in one warp (32 lanes x 8 chunks)
    const unsigned FULL = 0xffffffffu;
    float aval[2][8];
#pragma unroll
    for (int u = 0; u < 2; u++) {
        float mx = -CUDART_INF_F;
#pragma unroll
        for (int c = 0; c < 8; c++) mx = fmaxf(mx, sc[u][c]);
#pragma unroll
        for (int o = 16; o > 0; o >>= 1) mx = fmaxf(mx, __shfl_xor_sync(FULL, mx, o));
        float sum = 0.f;
#pragma unroll
        for (int c = 0; c < 8; c++) {
            float e = __expf(sc[u][c] - mx);
            aval[u][c] = e;
            sum += e;
        }
#pragma unroll
        for (int o = 16; o > 0; o >>= 1) sum += __shfl_xor_sync(FULL, sum, o);
        float r = 1.f / sum;
#pragma unroll
        for (int c = 0; c < 8; c++) aval[u][c] *= r;
    }

    // publish a to smem (reuses m_s; score reads finished)
    __syncthreads();
#pragma unroll
    for (int u = 0; u < 2; u++)
#pragma unroll
        for (int c = 0; c < 8; c++)
            av_s[(u * 8 + h) * 256 + c * 32 + sl] = aval[u][c];
    __syncthreads();

    // o = a @ v : lane owns d = {2sl,2sl+1}; a via warp-uniform LDS broadcast
    const float* avh0 = av_s + (0 * 8 + h) * 256;
    const float* avh1 = av_s + (1 * 8 + h) * 256;
    ull o0a = pk2(0.f, 0.f), o0b = o0a, o1a = o0a, o1b = o0a;
#pragma unroll 4
    for (int s2 = 0; s2 < 256; s2 += 2) {
        ull v0 = *(const ull*)(vbase + (size_t)s2 * D_ + 2 * sl);
        ull v1 = *(const ull*)(vbase + (size_t)(s2 + 1) * D_ + 2 * sl);
        float a00 = avh0[s2], a01 = avh0[s2 + 1];
        float a10 = avh1[s2], a11 = avh1[s2 + 1];
        o0a = ffma2(pk2(a00, a00), v0, o0a);
        o0b = ffma2(pk2(a01, a01), v1, o0b);
        o1a = ffma2(pk2(a10, a10), v0, o1a);
        o1b = ffma2(pk2(a11, a11), v1, o1b);
    }
    ull oa0 = fadd2(o0a, o0b), oa1 = fadd2(o1a, o1b);
    *(ull*)&g_o[((size_t)(b * T_ + t0 + 0) * H_ + h) * D_ + 2 * sl] = oa0;
    *(ull*)&g_o[((size_t)(b * T_ + t0 + 1) * H_ + h) * D_ + 2 * sl] = oa1;

    // attn_weights: reduce over heads (reads av_s, already published)
#pragma unroll
    for (int u = 0; u < 2; u++) {
        float acc = 0.f;
#pragma unroll
        for (int hh = 0; hh < 8; hh++) acc += av_s[(u * 8 + hh) * 256 + tid];
        outw[AW_OFF + (size_t)(b * T_ + t0 + u) * T_ + tid] = acc * 0.125f;
    }
}

// ---------------------------------------------------------------------------
extern "C" void kernel_launch(void* const* d_in, const int* in_sizes, int n_in,
                              void* d_out, int out_size)
{
    const float* x    = (const float*)d_in[0];
    const float* am   = (const float*)d_in[1];
    const float* pm   = (const float*)d_in[2];
    const float* Wqkv = (const float*)d_in[3];
    const float* bqkv = (const float*)d_in[4];
    const float* Wo   = (const float*)d_in[5];
    const float* bo   = (const float*)d_in[6];
    float* out = (float*)d_out;

    gemm_kernel<64, 4><<<dim3(24, 8), 256>>>(x, Wqkv, bqkv, nullptr, 1536, 0);
    attn_kernel<<<256, 256>>>(am, pm, out);
    gemm_kernel<32, 2><<<dim3(8, 16), 256>>>(nullptr, Wo, bo, out, 512, 1);
}